// round 2
// baseline (speedup 1.0000x reference)
#include <cuda_runtime.h>

// ---------------------------------------------------------------------------
// Problem constants
// ---------------------------------------------------------------------------
#define TT   512
#define BB   1024
#define IN1  80
#define NH1  100
#define NG1  400
#define NH2  50
#define NG2  200

typedef unsigned long long ull;

// ---------------------------------------------------------------------------
// Device scratch (__device__ globals are the sanctioned scratch mechanism)
// ---------------------------------------------------------------------------
__device__ __align__(16) float g_pre1[(size_t)BB * TT * NG1];   // 838.9 MB
__device__ __align__(16) float g_h1  [(size_t)BB * TT * NH1];   // 209.7 MB
__device__ __align__(16) float g_pre2[(size_t)BB * TT * NG2];   // 419.4 MB

__device__ __align__(16) float g_wih1T[IN1 * NG1];   // [k][g]
__device__ __align__(16) float g_whh1T[NH1 * NG1];
__device__ __align__(16) float g_wih2T[NH1 * NG2];
__device__ __align__(16) float g_whh2T[NH2 * NG2];
__device__ __align__(16) float g_b1[NG1];
__device__ __align__(16) float g_b2[NG2];

// ---------------------------------------------------------------------------
// f32x2 helpers (FFMA2 only reachable via PTX fma.rn.f32x2; bit-exact vs FFMA)
// ---------------------------------------------------------------------------
__device__ __forceinline__ ull ffma2(ull d, ull a, ull b) {
    asm("fma.rn.f32x2 %0, %1, %2, %0;" : "+l"(d) : "l"(a), "l"(b));
    return d;
}
__device__ __forceinline__ ull dup2(float x) {
    ull r; unsigned u = __float_as_uint(x);
    asm("mov.b64 %0, {%1, %1};" : "=l"(r) : "r"(u));
    return r;
}
__device__ __forceinline__ ull pk(float x, float y) {
    ull r;
    asm("mov.b64 %0, {%1, %2};" : "=l"(r) : "f"(x), "f"(y));
    return r;
}

// Fast-but-accurate activations (~1e-6 rel; NOT tanh.approx)
__device__ __forceinline__ float sigm(float x) {
    return __fdividef(1.0f, 1.0f + __expf(-x));
}
__device__ __forceinline__ float tanh_f(float x) {
    // 2*sigmoid(2x)-1; safe at both extremes (exp->inf gives exact -1)
    return __fdividef(2.0f, 1.0f + __expf(-2.0f * x)) - 1.0f;
}

// ---------------------------------------------------------------------------
// prep: transpose weights to [K][G], fuse biases
// ---------------------------------------------------------------------------
__global__ void prep_kernel(const float* __restrict__ Wih1, const float* __restrict__ Whh1,
                            const float* __restrict__ bih1, const float* __restrict__ bhh1,
                            const float* __restrict__ Wih2, const float* __restrict__ Whh2,
                            const float* __restrict__ bih2, const float* __restrict__ bhh2) {
    int tid = blockIdx.x * blockDim.x + threadIdx.x;
    int stride = gridDim.x * blockDim.x;
    for (int i = tid; i < IN1 * NG1; i += stride) { int k = i / NG1, g = i % NG1; g_wih1T[i] = Wih1[g * IN1 + k]; }
    for (int i = tid; i < NH1 * NG1; i += stride) { int k = i / NG1, g = i % NG1; g_whh1T[i] = Whh1[g * NH1 + k]; }
    for (int i = tid; i < NH1 * NG2; i += stride) { int k = i / NG2, g = i % NG2; g_wih2T[i] = Wih2[g * NH1 + k]; }
    for (int i = tid; i < NH2 * NG2; i += stride) { int k = i / NG2, g = i % NG2; g_whh2T[i] = Whh2[g * NH2 + k]; }
    for (int i = tid; i < NG1; i += stride) g_b1[i] = bih1[i] + bhh1[i];
    for (int i = tid; i < NG2; i += stride) g_b2[i] = bih2[i] + bhh2[i];
}

// ---------------------------------------------------------------------------
// GEMM: out[m][G] = x[m][K] @ wT[K][G] + bias ; 32 rows per CTA.
// Thread layout: G workers = 2 row-halves (16 rows) x (G/2) column-pairs.
// x tile staged duplicated ((v,v) ull) so FFMA2 a-operand is one LDS.64.
// ---------------------------------------------------------------------------
template<int K, int G>
__global__ __launch_bounds__(512, 1)
void gemm_kernel(const float* __restrict__ x, const float* __restrict__ wT,
                 const float* __restrict__ bias, float* __restrict__ out) {
    constexpr int NP = G / 2;
    extern __shared__ float sm[];
    float* sw = sm;                       // K*G floats
    ull*   sx = (ull*)(sm + K * G);       // 32*K dup pairs

    int tid = threadIdx.x;
    int m0  = blockIdx.x * 32;

    for (int i = tid; i < K * G; i += blockDim.x) sw[i] = wT[i];
    for (int i = tid; i < 32 * K; i += blockDim.x) {
        float v = x[(size_t)(m0 + i / K) * K + (i % K)];
        sx[i] = dup2(v);
    }
    __syncthreads();

    if (tid < G) {
        int half = tid / NP;
        int c    = tid - half * NP;
        int rb   = half * 16;
        const ull* swp = (const ull*)sw;   // [k][pair]

        ull bini = pk(bias[2 * c], bias[2 * c + 1]);
        ull acc[16];
#pragma unroll
        for (int r = 0; r < 16; r++) acc[r] = bini;

#pragma unroll 4
        for (int k = 0; k < K; k++) {
            ull w2 = swp[k * NP + c];
#pragma unroll
            for (int r = 0; r < 16; r++)
                acc[r] = ffma2(acc[r], sx[(rb + r) * K + k], w2);
        }
#pragma unroll
        for (int r = 0; r < 16; r++)
            *(ull*)(out + (size_t)(m0 + rb + r) * G + 2 * c) = acc[r];
    }
}

// ---------------------------------------------------------------------------
// Persistent LSTM: NB=8 batch rows per CTA, WhhT resident in smem.
// Gate phase: NP workers = 2 row-halves(4 rows) x (NP/2) groups of 2 col-pairs.
//   per k: 1 LDS.128 (w, 2 pairs) + 4 LDS.64 (h dup) + 8 FFMA2  -> pipe-bound.
// Update phase: NP threads x 4 units; c in registers; h -> smem dup + gmem.
// Next-step pre prefetched (LDG.128) during the gate phase.
// ---------------------------------------------------------------------------
template<int H, int NB, bool LAST_ONLY>
__global__ __launch_bounds__(256, 1)
void lstm_kernel(const float* __restrict__ pre, const float* __restrict__ whhT,
                 float* __restrict__ hout) {
    constexpr int G    = 4 * H;
    constexpr int NP   = G / 2;      // column pairs (200 / 100)
    constexpr int NGRP = NP / 2;     // groups of 2 pairs (100 / 50)
    constexpr int UPN  = NB * H;     // h units per CTA (800 / 400)
    constexpr int UPT  = UPN / NP;   // units per thread (4)

    extern __shared__ float sm[];
    float* sw  = sm;                          // H*G floats  (WhhT)
    float* sgf = sm + H * G;                  // NB*G floats (gates staging)
    ull*   sgu = (ull*)sgf;
    ull*   shd = (ull*)(sgf + NB * G);        // NB*H dup'd h

    int tid = threadIdx.x;
    int b0  = blockIdx.x * NB;

    for (int i = tid; i < H * G; i += blockDim.x) sw[i] = whhT[i];
    for (int i = tid; i < NB * H; i += blockDim.x) shd[i] = 0ULL;
    __syncthreads();

    bool gate = (tid < NP);
    int hh = 0, grp = 0;
    if (gate) { hh = tid / NGRP; grp = tid - hh * NGRP; }
    const ull* swp = (const ull*)sw;

    float cst[UPT];
#pragma unroll
    for (int u = 0; u < UPT; u++) cst[u] = 0.0f;

    ull pn[4][2];
    if (gate) {
#pragma unroll
        for (int r = 0; r < 4; r++) {
            const float4 v = *(const float4*)(pre + ((size_t)(b0 + hh * 4 + r) * TT) * G + 4 * grp);
            pn[r][0] = pk(v.x, v.y); pn[r][1] = pk(v.z, v.w);
        }
    }

    for (int t = 0; t < TT; t++) {
        if (gate) {
            ull acc[4][2];
#pragma unroll
            for (int r = 0; r < 4; r++) { acc[r][0] = pn[r][0]; acc[r][1] = pn[r][1]; }

            // prefetch next step's pre (clamped at the end; result unused then)
            int tn = (t + 1 < TT) ? t + 1 : t;
#pragma unroll
            for (int r = 0; r < 4; r++) {
                const float4 v = *(const float4*)(pre + ((size_t)(b0 + hh * 4 + r) * TT + tn) * G + 4 * grp);
                pn[r][0] = pk(v.x, v.y); pn[r][1] = pk(v.z, v.w);
            }

#pragma unroll 2
            for (int k = 0; k < H; k++) {
                ulonglong2 w = *(const ulonglong2*)(swp + k * NP + 2 * grp);
#pragma unroll
                for (int r = 0; r < 4; r++) {
                    ull h2 = shd[(hh * 4 + r) * H + k];
                    acc[r][0] = ffma2(acc[r][0], h2, w.x);
                    acc[r][1] = ffma2(acc[r][1], h2, w.y);
                }
            }
#pragma unroll
            for (int r = 0; r < 4; r++) {
                sgu[(hh * 4 + r) * NP + 2 * grp]     = acc[r][0];
                sgu[(hh * 4 + r) * NP + 2 * grp + 1] = acc[r][1];
            }
        }
        __syncthreads();

        if (tid < NP) {
#pragma unroll
            for (int u = 0; u < UPT; u++) {
                int id = u * NP + tid;
                int r  = id / H;
                int j  = id - r * H;
                const float* gr = sgf + r * G;
                float ig = sigm(gr[j]);
                float fg = sigm(gr[H + j]);
                float gg = tanh_f(gr[2 * H + j]);
                float og = sigm(gr[3 * H + j]);
                float c  = fg * cst[u] + ig * gg;
                cst[u] = c;
                float h  = og * tanh_f(c);
                shd[r * H + j] = dup2(h);
                if (!LAST_ONLY) {
                    hout[((size_t)(b0 + r) * TT + t) * H + j] = h;
                } else if (t == TT - 1) {
                    hout[(size_t)(b0 + r) * H + j] = h;
                }
            }
        }
        __syncthreads();
    }
}

// ---------------------------------------------------------------------------
// Launch
// ---------------------------------------------------------------------------
extern "C" void kernel_launch(void* const* d_in, const int* in_sizes, int n_in,
                              void* d_out, int out_size) {
    const float* x    = (const float*)d_in[0];
    const float* Wih1 = (const float*)d_in[1];
    const float* Whh1 = (const float*)d_in[2];
    const float* bih1 = (const float*)d_in[3];
    const float* bhh1 = (const float*)d_in[4];
    const float* Wih2 = (const float*)d_in[5];
    const float* Whh2 = (const float*)d_in[6];
    const float* bih2 = (const float*)d_in[7];
    const float* bhh2 = (const float*)d_in[8];
    float* out = (float*)d_out;
    (void)in_sizes; (void)n_in; (void)out_size;

    void *pre1, *h1, *pre2, *wih1T, *whh1T, *wih2T, *whh2T, *b1, *b2;
    cudaGetSymbolAddress(&pre1,  g_pre1);
    cudaGetSymbolAddress(&h1,    g_h1);
    cudaGetSymbolAddress(&pre2,  g_pre2);
    cudaGetSymbolAddress(&wih1T, g_wih1T);
    cudaGetSymbolAddress(&whh1T, g_whh1T);
    cudaGetSymbolAddress(&wih2T, g_wih2T);
    cudaGetSymbolAddress(&whh2T, g_whh2T);
    cudaGetSymbolAddress(&b1,    g_b1);
    cudaGetSymbolAddress(&b2,    g_b2);

    const int SMEM_G1 = IN1 * NG1 * 4 + 32 * IN1 * 8;          // 148480
    const int SMEM_G2 = NH1 * NG2 * 4 + 32 * NH1 * 8;          // 105600
    const int SMEM_L1 = NH1 * NG1 * 4 + 8 * NG1 * 4 + 8 * NH1 * 8;  // 179200
    const int SMEM_L2 = NH2 * NG2 * 4 + 8 * NG2 * 4 + 8 * NH2 * 8;  // 49600

    cudaFuncSetAttribute(gemm_kernel<IN1, NG1>, cudaFuncAttributeMaxDynamicSharedMemorySize, SMEM_G1);
    cudaFuncSetAttribute(gemm_kernel<NH1, NG2>, cudaFuncAttributeMaxDynamicSharedMemorySize, SMEM_G2);
    cudaFuncSetAttribute(lstm_kernel<NH1, 8, false>, cudaFuncAttributeMaxDynamicSharedMemorySize, SMEM_L1);
    cudaFuncSetAttribute(lstm_kernel<NH2, 8, true>,  cudaFuncAttributeMaxDynamicSharedMemorySize, SMEM_L2);

    prep_kernel<<<96, 256>>>(Wih1, Whh1, bih1, bhh1, Wih2, Whh2, bih2, bhh2);

    gemm_kernel<IN1, NG1><<<BB * TT / 32, 416, SMEM_G1>>>(
        x, (const float*)wih1T, (const float*)b1, (float*)pre1);

    lstm_kernel<NH1, 8, false><<<BB / 8, 224, SMEM_L1>>>(
        (const float*)pre1, (const float*)whh1T, (float*)h1);

    gemm_kernel<NH1, NG2><<<BB * TT / 32, 224, SMEM_G2>>>(
        (const float*)h1, (const float*)wih2T, (const float*)b2, (float*)pre2);

    lstm_kernel<NH2, 8, true><<<BB / 8, 128, SMEM_L2>>>(
        (const float*)pre2, (const float*)whh2T, out);
}